// round 15
// baseline (speedup 1.0000x reference)
#include <cuda_runtime.h>
#include <cuda_fp16.h>
#include <mma.h>
#include <stdint.h>
#include <math.h>

using namespace nvcuda;

constexpr int N      = 8192;
constexpr int WORDS  = N / 32;
constexpr int KSPLIT = 4;

// ---------------------------------------------------------------------------
// Scratch
// ---------------------------------------------------------------------------
__device__ uint32_t       g_bits[(size_t)N * WORDS];   // 8 MB adjacency bitmask
__device__ float          g_dinv[N];
__device__ unsigned int   g_absmax[4];                 // per-layer max|ydraw|
__device__ float          g_ydf0[(size_t)N * 128];     // raw Y@W ping
__device__ float          g_ydf1[(size_t)N * 128];     // raw Y@W pong
__device__ __half         g_ydh[(size_t)N * 128];      // fp16 operand (scaled)
__device__ float          g_part[(size_t)KSPLIT * N * 128];
__device__ __half         g_reh[(size_t)N * 64];       // re * 64 (fp16)

// ---------------------------------------------------------------------------
// streams/events (static init; falls back to serial)
// ---------------------------------------------------------------------------
struct OverlapCtx {
    cudaStream_t s2 = nullptr;
    cudaEvent_t  evFork1 = nullptr, evJoin1 = nullptr;
    cudaEvent_t  evFork2 = nullptr, evJoin2 = nullptr;
    bool ok = false;
    OverlapCtx() {
        ok = (cudaStreamCreateWithFlags(&s2, cudaStreamNonBlocking) == cudaSuccess) &&
             (cudaEventCreateWithFlags(&evFork1, cudaEventDisableTiming) == cudaSuccess) &&
             (cudaEventCreateWithFlags(&evJoin1, cudaEventDisableTiming) == cudaSuccess) &&
             (cudaEventCreateWithFlags(&evFork2, cudaEventDisableTiming) == cudaSuccess) &&
             (cudaEventCreateWithFlags(&evJoin2, cudaEventDisableTiming) == cudaSuccess);
    }
};
static OverlapCtx g_ov;

// ---------------------------------------------------------------------------
// helpers
// ---------------------------------------------------------------------------
__device__ __forceinline__ void cp16(void* smem_dst, const void* gsrc) {
    uint32_t d = (uint32_t)__cvta_generic_to_shared(smem_dst);
    asm volatile("cp.async.cg.shared.global [%0], [%1], 16;\n" :: "r"(d), "l"(gsrc));
}
__device__ __forceinline__ void cp_commit() {
    asm volatile("cp.async.commit_group;\n" ::: "memory");
}
__device__ __forceinline__ void cp_wait0() {
    asm volatile("cp.async.wait_group 0;\n" ::: "memory");
}
__device__ __forceinline__ float layer_scale(int slot) {
    float m = __uint_as_float(g_absmax[slot]);
    int e; frexpf(m, &e);
    return ldexpf(1.f, 11 - e);
}
__device__ __forceinline__ float layer_inv_scale(int slot) {
    float m = __uint_as_float(g_absmax[slot]);
    int e; frexpf(m, &e);
    return ldexpf(1.f, e - 11);
}

// ---------------------------------------------------------------------------
// 1) Prep: bitmask + dinv (+ absmax reset). int4 loads + shfl-OR packing.
// ---------------------------------------------------------------------------
__global__ void __launch_bounds__(256) prep_kernel(const int* __restrict__ edge) {
    int row  = blockIdx.x;
    int lane = threadIdx.x & 31;
    int warp = threadIdx.x >> 5;
    __shared__ int wcnt[8];

    if (blockIdx.x == 0 && threadIdx.x < 4) g_absmax[threadIdx.x] = 0u;

    const int4* erow = (const int4*)(edge + (size_t)row * N) + warp * 256;
    int cnt = 0;
#pragma unroll
    for (int it = 0; it < 8; ++it) {
        int4 v = erow[it * 32 + lane];
        uint32_t nib = (v.x != 0 ? 1u : 0u) | (v.y != 0 ? 2u : 0u) |
                       (v.z != 0 ? 4u : 0u) | (v.w != 0 ? 8u : 0u);
        uint32_t wbits = nib << (4 * (lane & 7));
        wbits |= __shfl_xor_sync(0xFFFFFFFFu, wbits, 1);
        wbits |= __shfl_xor_sync(0xFFFFFFFFu, wbits, 2);
        wbits |= __shfl_xor_sync(0xFFFFFFFFu, wbits, 4);
        if ((lane & 7) == 0) {
            g_bits[(size_t)row * WORDS + warp * 32 + it * 4 + (lane >> 3)] = wbits;
            cnt += __popc(wbits);
        }
    }
    cnt += __shfl_xor_sync(0xFFFFFFFFu, cnt, 8);
    cnt += __shfl_xor_sync(0xFFFFFFFFu, cnt, 16);
    if (lane == 0) wcnt[warp] = cnt;
    __syncthreads();
    if (threadIdx.x == 0) {
        int deg = 1;
#pragma unroll
        for (int i = 0; i < 8; ++i) deg += wcnt[i];
        g_dinv[row] = rsqrtf((float)deg);
    }
}

// ---------------------------------------------------------------------------
// 2) small GEMM (layer-1 only): ydraw = x @ W1 -> g_ydf0 + absmax[0]
// ---------------------------------------------------------------------------
template <int KIN, int COUT>
__global__ void __launch_bounds__(256) small_gemm8(const float* __restrict__ act,
                                                   const float* __restrict__ Wa,
                                                   int slot) {
    __shared__ float sW[KIN * COUT];
    __shared__ float sact[16 * KIN];
    __shared__ unsigned int samax;

    int tid = threadIdx.x;
    if (tid == 0) samax = 0u;
    for (int i = tid; i < KIN * COUT; i += 256) sW[i] = Wa[i];

    int rbase = blockIdx.x * 16;
    for (int j = tid; j < 16 * KIN; j += 256)
        sact[j] = act[(size_t)rbase * KIN + j];
    __syncthreads();

    constexpr int TPR = COUT / 4;
    constexpr int RPI = 256 / TPR;
    int c4 = (tid % TPR) * 4;
    int ry0 = tid / TPR;
    float amax = 0.f;

#pragma unroll
    for (int it = 0; it < 16; it += RPI) {
        int ry = it + ry0;
        const float* sa = &sact[ry * KIN];
        float4 a0 = make_float4(0.f, 0.f, 0.f, 0.f);
        float4 a1 = make_float4(0.f, 0.f, 0.f, 0.f);
#pragma unroll
        for (int k = 0; k < KIN; k += 2) {
            float v0 = sa[k], v1 = sa[k + 1];
            float4 w0 = *(const float4*)&sW[k * COUT + c4];
            float4 w1 = *(const float4*)&sW[(k + 1) * COUT + c4];
            a0.x = fmaf(v0, w0.x, a0.x); a0.y = fmaf(v0, w0.y, a0.y);
            a0.z = fmaf(v0, w0.z, a0.z); a0.w = fmaf(v0, w0.w, a0.w);
            a1.x = fmaf(v1, w1.x, a1.x); a1.y = fmaf(v1, w1.y, a1.y);
            a1.z = fmaf(v1, w1.z, a1.z); a1.w = fmaf(v1, w1.w, a1.w);
        }
        int row = rbase + ry;
        float4 y;
        y.x = a0.x + a1.x; y.y = a0.y + a1.y;
        y.z = a0.z + a1.z; y.w = a0.w + a1.w;
        *(float4*)&g_ydf0[(size_t)row * COUT + c4] = y;
        amax = fmaxf(amax, fmaxf(fmaxf(fabsf(y.x), fabsf(y.y)),
                                 fmaxf(fabsf(y.z), fabsf(y.w))));
    }
    atomicMax(&samax, __float_as_uint(amax));
    __syncthreads();
    if (tid == 0) atomicMax(&g_absmax[slot], samax);
}

// ---------------------------------------------------------------------------
// 2b) convert: ydh = fp16(ydraw * dinv[row] * scale[slot])
// ---------------------------------------------------------------------------
__global__ void __launch_bounds__(256) convert_kernel(int slot, int C, int sel) {
    const float* ydf = sel ? g_ydf1 : g_ydf0;
    float s = layer_scale(slot);
    size_t i = ((size_t)blockIdx.x * 256 + threadIdx.x) * 4;
    int row = (int)(i / C);
    float ds = g_dinv[row] * s;
    float4 y = *(const float4*)&ydf[i];
    __half2 p01 = __floats2half2_rn(y.x * ds, y.y * ds);
    __half2 p23 = __floats2half2_rn(y.z * ds, y.w * ds);
    *(uint2*)&g_ydh[i] = make_uint2(*(uint32_t*)&p01, *(uint32_t*)&p23);
}

// ---------------------------------------------------------------------------
// 3) big adjacency GEMM (fp16 wmma): BM=128 x BN, split-K=4.
// ---------------------------------------------------------------------------
template <int BN, int MAXCTA>
__global__ void __launch_bounds__(256, MAXCTA) big_gcn9() {
    constexpr int BM    = 128;
    constexpr int KC    = 64;
    constexpr int NC    = (N / KSPLIT) / KC;
    constexpr int LDA   = 72;
    constexpr int LDB   = BN + 8;
    constexpr int ASZ   = BM * LDA;
    constexpr int BSZ   = KC * LDB;
    constexpr int WCOLS = (BN == 64) ? 2 : 4;
    constexpr int WROWS = 8 / WCOLS;
    constexpr int WM    = BM / WROWS;
    constexpr int WN    = BN / WCOLS;
    constexpr int FM    = WM / 16;
    constexpr int FN    = WN / 16;
    constexpr int SEG   = BN / 8;
    constexpr int CPB   = KC * SEG / 256;

    extern __shared__ __align__(16) __half smem[];
    __half* sA = smem;
    __half* sB = smem + 2 * ASZ;

    int tid  = threadIdx.x;
    int warp = tid >> 5;
    int wr   = warp / WCOLS;
    int wc   = warp % WCOLS;
    int r0   = blockIdx.x * BM;
    int ks0  = blockIdx.z * (N / KSPLIT);

    int arow = tid >> 1;
    const uint32_t* wptr = &g_bits[(size_t)(r0 + arow) * WORDS + (ks0 >> 5) + (tid & 1)];
    uint32_t abase = (uint32_t)__cvta_generic_to_shared(&sA[arow * LDA + (tid & 1) * 32]);

    wmma::fragment<wmma::accumulator, 16, 16, 16, float> acc[FM][FN];
#pragma unroll
    for (int fm = 0; fm < FM; ++fm)
#pragma unroll
        for (int fn = 0; fn < FN; ++fn) wmma::fill_fragment(acc[fm][fn], 0.f);

    auto fetchB = [&](int ch, int buf) {
        int k0 = ks0 + ch * KC;
#pragma unroll
        for (int i = 0; i < CPB; ++i) {
            int s = tid + i * 256;
            int row = s / SEG, seg = s % SEG;
            cp16(&sB[buf * BSZ + row * LDB + seg * 8],
                 &g_ydh[(size_t)(k0 + row) * BN + seg * 8]);
        }
        cp_commit();
    };
    auto storeA = [&](uint32_t w, int buf) {
        uint32_t base = abase + buf * (ASZ * 2);
#pragma unroll
        for (int j = 0; j < 4; ++j) {
            uint32_t bb = w >> (j * 8);
            uint4 u;
            u.x = ((bb & 1u)  ? 0x3C00u : 0u) | ((bb & 2u)   ? 0x3C000000u : 0u);
            u.y = ((bb & 4u)  ? 0x3C00u : 0u) | ((bb & 8u)   ? 0x3C000000u : 0u);
            u.z = ((bb & 16u) ? 0x3C00u : 0u) | ((bb & 32u)  ? 0x3C000000u : 0u);
            u.w = ((bb & 64u) ? 0x3C00u : 0u) | ((bb & 128u) ? 0x3C000000u : 0u);
            asm volatile("st.shared.v4.b32 [%0], {%1, %2, %3, %4};"
                         :: "r"(base + j * 16), "r"(u.x), "r"(u.y), "r"(u.z), "r"(u.w));
        }
    };

    fetchB(0, 0);
    storeA(wptr[0], 0);
    cp_wait0();
    __syncthreads();

    int buf = 0;
    for (int ch = 0; ch < NC; ++ch) {
        int nbuf = buf ^ 1;
        uint32_t wnext = 0;
        if (ch + 1 < NC) {
            fetchB(ch + 1, nbuf);
            wnext = wptr[(ch + 1) * 2];
        }
#pragma unroll
        for (int ks = 0; ks < 4; ++ks) {
            wmma::fragment<wmma::matrix_a, 16, 16, 16, __half, wmma::row_major> a[FM];
#pragma unroll
            for (int fm = 0; fm < FM; ++fm)
                wmma::load_matrix_sync(a[fm],
                    &sA[buf * ASZ + (wr * WM + fm * 16) * LDA + ks * 16], LDA);
#pragma unroll
            for (int fn = 0; fn < FN; ++fn) {
                wmma::fragment<wmma::matrix_b, 16, 16, 16, __half, wmma::row_major> b;
                int bcol = wc * WN + fn * 16;
                wmma::load_matrix_sync(b, &sB[buf * BSZ + (ks * 16) * LDB + bcol], LDB);
#pragma unroll
                for (int fm = 0; fm < FM; ++fm)
                    wmma::mma_sync(acc[fm][fn], a[fm], b, acc[fm][fn]);
            }
        }
        if (ch + 1 < NC) {
            storeA(wnext, nbuf);
            cp_wait0();
        }
        __syncthreads();
        buf = nbuf;
    }

    float* pout = &g_part[(size_t)blockIdx.z * N * BN];
#pragma unroll
    for (int fm = 0; fm < FM; ++fm)
#pragma unroll
        for (int fn = 0; fn < FN; ++fn)
            wmma::store_matrix_sync(
                &pout[(size_t)(r0 + wr * WM + fm * 16) * BN + wc * WN + fn * 16],
                acc[fm][fn], BN, wmma::mem_row_major);
}

constexpr int SMEM_BG9_128 = (2 * 128 * 72 + 2 * 64 * 136) * 2;  // 71680 B
constexpr int SMEM_BG9_64  = (2 * 128 * 72 + 2 * 64 * 72) * 2;   // 55296 B

// ---------------------------------------------------------------------------
// 3c) FUSED: combine(layer k) + small GEMM(layer k+1).
//     act = lrelu(di*inv*Σpart + di²*ydraw + bias)  (16 rows, CIN cols, in smem)
//     then ydraw_next[16, COUT] = act[:, act_c0:act_c0+KIN] @ W
// ---------------------------------------------------------------------------
template <int CIN, int KIN, int COUT>
__global__ void __launch_bounds__(256) fused_kernel(const float* __restrict__ bias_a,
                                                    const float* __restrict__ bias_b,
                                                    int bsplit, int slot_in, int slot_out,
                                                    const float* __restrict__ Wa,
                                                    const float* __restrict__ Wb,
                                                    float* act_store, int emit_reh,
                                                    int in_sel, int act_c0) {
    __shared__ float sW[KIN * COUT];
    __shared__ float sact[16 * CIN];
    __shared__ unsigned int samax;

    const float* ydin = in_sel ? g_ydf1 : g_ydf0;
    float* ydout = in_sel ? g_ydf0 : g_ydf1;   // ping-pong

    int tid = threadIdx.x;
    if (tid == 0) samax = 0u;
    if (Wb == nullptr) {
        for (int i = tid; i < KIN * COUT; i += 256) sW[i] = Wa[i];
    } else {
        for (int i = tid; i < KIN * COUT; i += 256) {
            int k = i / COUT, c = i % COUT;
            sW[i] = (c < 64) ? Wa[k * 64 + c] : Wb[k * 64 + (c - 64)];
        }
    }

    // ---- combine into sact ----
    float inv = layer_inv_scale(slot_in);
    int rbase = blockIdx.x * 16;
    constexpr int Q = 16 * CIN / 4;   // float4 count
    for (int idx = tid; idx < Q; idx += 256) {
        int r  = idx / (CIN / 4);
        int c4 = (idx % (CIN / 4)) * 4;
        int row = rbase + r;
        float di  = g_dinv[row];
        float dii = di * di;
        float dis = di * inv;
        size_t o = (size_t)row * CIN + c4;
        float4 p = make_float4(0.f, 0.f, 0.f, 0.f);
#pragma unroll
        for (int pz = 0; pz < KSPLIT; ++pz) {
            float4 pp = *(const float4*)&g_part[(size_t)pz * N * CIN + o];
            p.x += pp.x; p.y += pp.y; p.z += pp.z; p.w += pp.w;
        }
        float4 yd = *(const float4*)&ydin[o];
        const float* bias = (c4 < bsplit) ? bias_a : bias_b;
        int bo = (c4 < bsplit) ? c4 : c4 - bsplit;
        float4 v;
        v.x = p.x * dis + yd.x * dii + bias[bo + 0];
        v.y = p.y * dis + yd.y * dii + bias[bo + 1];
        v.z = p.z * dis + yd.z * dii + bias[bo + 2];
        v.w = p.w * dis + yd.w * dii + bias[bo + 3];
        v.x = (v.x > 0.f) ? v.x : 0.01f * v.x;
        v.y = (v.y > 0.f) ? v.y : 0.01f * v.y;
        v.z = (v.z > 0.f) ? v.z : 0.01f * v.z;
        v.w = (v.w > 0.f) ? v.w : 0.01f * v.w;
        *(float4*)&sact[r * CIN + c4] = v;
        if (act_store) *(float4*)&act_store[o] = v;
        if (emit_reh && c4 < 64) {
            __half2 h01 = __floats2half2_rn(v.x * 64.f, v.y * 64.f);
            __half2 h23 = __floats2half2_rn(v.z * 64.f, v.w * 64.f);
            *(uint2*)&g_reh[(size_t)row * 64 + c4] =
                make_uint2(*(uint32_t*)&h01, *(uint32_t*)&h23);
        }
    }
    __syncthreads();

    // ---- small GEMM from sact ----
    constexpr int TPR = COUT / 4;
    constexpr int RPI = 256 / TPR;
    int c4 = (tid % TPR) * 4;
    int ry0 = tid / TPR;
    float amax = 0.f;

#pragma unroll
    for (int it = 0; it < 16; it += RPI) {
        int ry = it + ry0;
        const float* sa = &sact[ry * CIN + act_c0];
        float4 a0 = make_float4(0.f, 0.f, 0.f, 0.f);
        float4 a1 = make_float4(0.f, 0.f, 0.f, 0.f);
#pragma unroll
        for (int k = 0; k < KIN; k += 2) {
            float v0 = sa[k], v1 = sa[k + 1];
            float4 w0 = *(const float4*)&sW[k * COUT + c4];
            float4 w1 = *(const float4*)&sW[(k + 1) * COUT + c4];
            a0.x = fmaf(v0, w0.x, a0.x); a0.y = fmaf(v0, w0.y, a0.y);
            a0.z = fmaf(v0, w0.z, a0.z); a0.w = fmaf(v0, w0.w, a0.w);
            a1.x = fmaf(v1, w1.x, a1.x); a1.y = fmaf(v1, w1.y, a1.y);
            a1.z = fmaf(v1, w1.z, a1.z); a1.w = fmaf(v1, w1.w, a1.w);
        }
        int row = rbase + ry;
        float4 y;
        y.x = a0.x + a1.x; y.y = a0.y + a1.y;
        y.z = a0.z + a1.z; y.w = a0.w + a1.w;
        *(float4*)&ydout[(size_t)row * COUT + c4] = y;
        amax = fmaxf(amax, fmaxf(fmaxf(fabsf(y.x), fabsf(y.y)),
                                 fmaxf(fabsf(y.z), fabsf(y.w))));
    }
    atomicMax(&samax, __float_as_uint(amax));
    __syncthreads();
    if (tid == 0) atomicMax(&g_absmax[slot_out], samax);
}

// ---------------------------------------------------------------------------
// 3b) final combine (layer 5 -> xout)
// ---------------------------------------------------------------------------
__global__ void __launch_bounds__(256) combine_kernel(const float* __restrict__ bias,
                                                      int C, int slot, int in_sel,
                                                      float* __restrict__ out) {
    const float* ydin = in_sel ? g_ydf1 : g_ydf0;
    float inv = layer_inv_scale(slot);
    int i = blockIdx.x * 256 + threadIdx.x;
    int cq = C >> 2;
    int row = i / cq;
    int c4  = (i - row * cq) * 4;
    float di  = g_dinv[row];
    float dii = di * di;
    float dis = di * inv;
    size_t o = (size_t)row * C + c4;
    float4 p = make_float4(0.f, 0.f, 0.f, 0.f);
#pragma unroll
    for (int pz = 0; pz < KSPLIT; ++pz) {
        float4 pp = *(const float4*)&g_part[(size_t)pz * N * C + o];
        p.x += pp.x; p.y += pp.y; p.z += pp.z; p.w += pp.w;
    }
    float4 yd = *(const float4*)&ydin[o];
    float4 v;
    v.x = p.x * dis + yd.x * dii + bias[c4 + 0];
    v.y = p.y * dis + yd.y * dii + bias[c4 + 1];
    v.z = p.z * dis + yd.z * dii + bias[c4 + 2];
    v.w = p.w * dis + yd.w * dii + bias[c4 + 3];
    v.x = (v.x > 0.f) ? v.x : 0.01f * v.x;
    v.y = (v.y > 0.f) ? v.y : 0.01f * v.y;
    v.z = (v.z > 0.f) ? v.z : 0.01f * v.z;
    v.w = (v.w > 0.f) ? v.w : 0.01f * v.w;
    *(float4*)&out[o] = v;
}

// ---------------------------------------------------------------------------
// 5) recon = sigmoid((reh @ reh^T) / 4096), triangular 1-D grid, fp16
// ---------------------------------------------------------------------------
__device__ __forceinline__ float fsig(float x) {
    return __fdividef(1.f, 1.f + __expf(-x));
}

constexpr int RLD  = 72;
constexpr int RLDC = 132;
constexpr int SMEM_RECON = 128 * RLDC * 4;  // 67584 B

__global__ void __launch_bounds__(256, 2) recon_kernel(float* __restrict__ out) {
    int bid = blockIdx.x;
    int by = (int)((sqrtf(8.f * (float)bid + 1.f) - 1.f) * 0.5f);
    while ((by + 1) * (by + 2) / 2 <= bid) ++by;
    while (by * (by + 1) / 2 > bid) --by;
    int bx = bid - by * (by + 1) / 2;

    extern __shared__ __align__(16) __half smem2[];
    __half* sA = smem2;
    __half* sB = smem2 + 128 * RLD;

    int tid = threadIdx.x;
    int r0 = by * 128, c0 = bx * 128;

    int srow = tid >> 1;
    int soff = (tid & 1) * 32;
    {
        const uint4* s;
        uint4* d;
        s = (const uint4*)&g_reh[(size_t)(r0 + srow) * 64 + soff];
        d = (uint4*)&sA[srow * RLD + soff];
        d[0] = s[0]; d[1] = s[1]; d[2] = s[2]; d[3] = s[3];
        s = (const uint4*)&g_reh[(size_t)(c0 + srow) * 64 + soff];
        d = (uint4*)&sB[srow * RLD + soff];
        d[0] = s[0]; d[1] = s[1]; d[2] = s[2]; d[3] = s[3];
    }
    __syncthreads();

    int warp = tid >> 5;
    int lane = tid & 31;
    int wr = warp >> 2;
    int wc = warp & 3;

    wmma::fragment<wmma::accumulator, 16, 16, 16, float> acc[4][2];
#pragma unroll
    for (int fm = 0; fm < 4; ++fm)
#pragma unroll
        for (int fn = 0; fn < 2; ++fn) wmma::fill_fragment(acc[fm][fn], 0.f);

#pragma unroll
    for (int ks = 0; ks < 4; ++ks) {
        int k = ks * 16;
        wmma::fragment<wmma::matrix_a, 16, 16, 16, __half, wmma::row_major> a[4];
#pragma unroll
        for (int fm = 0; fm < 4; ++fm)
            wmma::load_matrix_sync(a[fm], &sA[(wr * 64 + fm * 16) * RLD + k], RLD);
#pragma unroll
        for (int fn = 0; fn < 2; ++fn) {
            int col = wc * 32 + fn * 16;
            wmma::fragment<wmma::matrix_b, 16, 16, 16, __half, wmma::col_major> b;
            wmma::load_matrix_sync(b, &sB[col * RLD + k], RLD);
#pragma unroll
            for (int fm = 0; fm < 4; ++fm)
                wmma::mma_sync(acc[fm][fn], a[fm], b, acc[fm][fn]);
        }
    }
    __syncthreads();

    float* sC = reinterpret_cast<float*>(smem2);
#pragma unroll
    for (int fm = 0; fm < 4; ++fm)
#pragma unroll
        for (int fn = 0; fn < 2; ++fn)
            wmma::store_matrix_sync(&sC[(wr * 64 + fm * 16) * RLDC + wc * 32 + fn * 16],
                                    acc[fm][fn], RLDC, wmma::mem_row_major);
    __syncthreads();

    constexpr float INVS = 1.f / 4096.f;
#pragma unroll
    for (int it = 0; it < 16; ++it) {
        int f4 = tid + it * 256;
        int r  = f4 >> 5;
        int c4 = (f4 & 31) << 2;
        float4 o;
        o.x = fsig(sC[r * RLDC + c4 + 0] * INVS);
        o.y = fsig(sC[r * RLDC + c4 + 1] * INVS);
        o.z = fsig(sC[r * RLDC + c4 + 2] * INVS);
        o.w = fsig(sC[r * RLDC + c4 + 3] * INVS);
        *(float4*)&out[(size_t)(r0 + r) * N + c0 + c4] = o;
    }
    if (bx != by) {
#pragma unroll
        for (int i = 0; i < 16; ++i) {
            int c = warp * 16 + i;
#pragma unroll
            for (int q = 0; q < 4; ++q) {
                float v = sC[c * RLDC + q * 32 + lane] * INVS;
                out[(size_t)(c0 + c) * N + r0 + q * 32 + lane] = fsig(v);
            }
        }
    }
}

// ---------------------------------------------------------------------------
// Launch chain.
// Fork 1: small_gemm (s2) ∥ prep (main).  Fork 2: recon (s2) ∥ layer-5 (main).
// big_gcn9<64,3> stays at launch #4 (profiled).
// ---------------------------------------------------------------------------
extern "C" void kernel_launch(void* const* d_in, const int* in_sizes, int n_in,
                              void* d_out, int out_size) {
    (void)in_sizes; (void)n_in; (void)out_size;
    const float* x    = (const float*)d_in[0];
    const int*   edge = (const int*)  d_in[1];
    const float* W1   = (const float*)d_in[2];
    const float* b1   = (const float*)d_in[3];
    const float* W2   = (const float*)d_in[4];
    const float* b2   = (const float*)d_in[5];
    const float* We   = (const float*)d_in[6];
    const float* be   = (const float*)d_in[7];
    const float* Wd1  = (const float*)d_in[8];
    const float* bd1  = (const float*)d_in[9];
    const float* Wd2  = (const float*)d_in[10];
    const float* bd2  = (const float*)d_in[11];

    float* out   = (float*)d_out;
    float* recon = out;
    float* xout  = out + (size_t)N * N;
    float* zout  = xout + (size_t)N * 128;

    cudaFuncSetAttribute(big_gcn9<128, 2>, cudaFuncAttributeMaxDynamicSharedMemorySize, SMEM_BG9_128);
    cudaFuncSetAttribute(big_gcn9<64, 3>,  cudaFuncAttributeMaxDynamicSharedMemorySize, SMEM_BG9_64);
    cudaFuncSetAttribute(recon_kernel,     cudaFuncAttributeMaxDynamicSharedMemorySize, SMEM_RECON);

    // ---- fork 1: layer-1 small_gemm (s2) ∥ prep (main) ----
    if (g_ov.ok) {
        cudaEventRecord(g_ov.evFork1, 0);
        cudaStreamWaitEvent(g_ov.s2, g_ov.evFork1, 0);
        small_gemm8<128, 64><<<512, 256, 0, g_ov.s2>>>(x, W1, 0);             // #1
        cudaEventRecord(g_ov.evJoin1, g_ov.s2);
        prep_kernel<<<N, 256>>>(edge);                                        // #2
        cudaStreamWaitEvent(0, g_ov.evJoin1, 0);
    } else {
        small_gemm8<128, 64><<<512, 256>>>(x, W1, 0);
        prep_kernel<<<N, 256>>>(edge);
    }
    convert_kernel<<<N * 64 / 1024, 256>>>(0, 64, 0);                         // #3
    big_gcn9<64, 3><<<dim3(64, 1, KSPLIT), 256, SMEM_BG9_64>>>();             // #4 <- profiled

    // fusedA: combine1 (h) + h@W2 -> ydf1, slot1
    fused_kernel<64, 64, 128><<<512, 256>>>(b1, b1, 64, 0, 1, W2, nullptr,
                                            nullptr, 0, 0, 0);                // #5
    convert_kernel<<<N * 128 / 1024, 256>>>(1, 128, 1);                       // #6
    big_gcn9<128, 2><<<dim3(64, 1, KSPLIT), 256, SMEM_BG9_128>>>();           // #7

    // fusedB: combine2 (z -> zout) + z@[We|Wd1] -> ydf0, slot2
    fused_kernel<128, 128, 128><<<512, 256>>>(b2, b2, 128, 1, 2, We, Wd1,
                                              zout, 0, 1, 0);                 // #8
    convert_kernel<<<N * 128 / 1024, 256>>>(2, 128, 0);                       // #9
    big_gcn9<128, 2><<<dim3(64, 1, KSPLIT), 256, SMEM_BG9_128>>>();           // #10

    // fusedC: combine3 ([re|xd]) + xd@Wd2 -> ydf1, slot3; emits g_reh inline
    fused_kernel<128, 64, 128><<<512, 256>>>(be, bd1, 64, 2, 3, Wd2, nullptr,
                                             nullptr, 1, 0, 64);              // #11

    constexpr int TRI = 64 * 65 / 2;   // 2080 tiles

    if (g_ov.ok) {
        // fork 2: recon (s2) ∥ layer-5 chain (main)
        cudaEventRecord(g_ov.evFork2, 0);
        cudaStreamWaitEvent(g_ov.s2, g_ov.evFork2, 0);
        recon_kernel<<<TRI, 256, SMEM_RECON, g_ov.s2>>>(recon);

        convert_kernel<<<N * 128 / 1024, 256>>>(3, 128, 1);
        big_gcn9<128, 2><<<dim3(64, 1, KSPLIT), 256, SMEM_BG9_128>>>();
        combine_kernel<<<N * 128 / 1024, 256>>>(bd2, 128, 3, 1, xout);

        cudaEventRecord(g_ov.evJoin2, g_ov.s2);
        cudaStreamWaitEvent(0, g_ov.evJoin2, 0);
    } else {
        convert_kernel<<<N * 128 / 1024, 256>>>(3, 128, 1);
        big_gcn9<128, 2><<<dim3(64, 1, KSPLIT), 256, SMEM_BG9_128>>>();
        combine_kernel<<<N * 128 / 1024, 256>>>(bd2, 128, 3, 1, xout);
        recon_kernel<<<TRI, 256, SMEM_RECON>>>(recon);
    }
}

// round 17
// speedup vs baseline: 1.1830x; 1.1830x over previous
#include <cuda_runtime.h>
#include <cuda_fp16.h>
#include <mma.h>
#include <stdint.h>
#include <math.h>

using namespace nvcuda;

constexpr int N      = 8192;
constexpr int WORDS  = N / 32;
constexpr int KSPLIT = 4;

// ---------------------------------------------------------------------------
// Scratch
// ---------------------------------------------------------------------------
__device__ uint32_t       g_bits[(size_t)N * WORDS];   // 8 MB adjacency bitmask
__device__ float          g_dinv[N];
__device__ unsigned int   g_absmax[4];                 // per-layer max|ydraw|
__device__ float          g_ydf0[(size_t)N * 128];     // raw Y@W ping
__device__ float          g_ydf1[(size_t)N * 128];     // raw Y@W pong
__device__ __half         g_ydh[(size_t)N * 128];      // fp16 operand (scaled)
__device__ float          g_part[(size_t)KSPLIT * N * 128];
__device__ __half         g_reh[(size_t)N * 64];       // re * 64 (fp16)

// ---------------------------------------------------------------------------
// streams/events (static init; falls back to serial)
// ---------------------------------------------------------------------------
struct OverlapCtx {
    cudaStream_t s2 = nullptr;
    cudaEvent_t  evFork1 = nullptr, evJoin1 = nullptr;
    cudaEvent_t  evFork2 = nullptr, evJoin2 = nullptr;
    bool ok = false;
    OverlapCtx() {
        ok = (cudaStreamCreateWithFlags(&s2, cudaStreamNonBlocking) == cudaSuccess) &&
             (cudaEventCreateWithFlags(&evFork1, cudaEventDisableTiming) == cudaSuccess) &&
             (cudaEventCreateWithFlags(&evJoin1, cudaEventDisableTiming) == cudaSuccess) &&
             (cudaEventCreateWithFlags(&evFork2, cudaEventDisableTiming) == cudaSuccess) &&
             (cudaEventCreateWithFlags(&evJoin2, cudaEventDisableTiming) == cudaSuccess);
    }
};
static OverlapCtx g_ov;

// ---------------------------------------------------------------------------
// helpers
// ---------------------------------------------------------------------------
__device__ __forceinline__ void cp16(void* smem_dst, const void* gsrc) {
    uint32_t d = (uint32_t)__cvta_generic_to_shared(smem_dst);
    asm volatile("cp.async.cg.shared.global [%0], [%1], 16;\n" :: "r"(d), "l"(gsrc));
}
__device__ __forceinline__ void cp_commit() {
    asm volatile("cp.async.commit_group;\n" ::: "memory");
}
__device__ __forceinline__ void cp_wait0() {
    asm volatile("cp.async.wait_group 0;\n" ::: "memory");
}
__device__ __forceinline__ float layer_scale(int slot) {
    float m = __uint_as_float(g_absmax[slot]);
    int e; frexpf(m, &e);
    return ldexpf(1.f, 11 - e);
}
__device__ __forceinline__ float layer_inv_scale(int slot) {
    float m = __uint_as_float(g_absmax[slot]);
    int e; frexpf(m, &e);
    return ldexpf(1.f, e - 11);
}

// ---------------------------------------------------------------------------
// 1) Prep: bitmask + dinv.  int4 loads + shfl-OR packing.
// ---------------------------------------------------------------------------
__global__ void __launch_bounds__(256) prep_kernel(const int* __restrict__ edge) {
    int row  = blockIdx.x;
    int lane = threadIdx.x & 31;
    int warp = threadIdx.x >> 5;
    __shared__ int wcnt[8];

    const int4* erow = (const int4*)(edge + (size_t)row * N) + warp * 256;
    int cnt = 0;
#pragma unroll
    for (int it = 0; it < 8; ++it) {
        int4 v = erow[it * 32 + lane];
        uint32_t nib = (v.x != 0 ? 1u : 0u) | (v.y != 0 ? 2u : 0u) |
                       (v.z != 0 ? 4u : 0u) | (v.w != 0 ? 8u : 0u);
        uint32_t wbits = nib << (4 * (lane & 7));
        wbits |= __shfl_xor_sync(0xFFFFFFFFu, wbits, 1);
        wbits |= __shfl_xor_sync(0xFFFFFFFFu, wbits, 2);
        wbits |= __shfl_xor_sync(0xFFFFFFFFu, wbits, 4);
        if ((lane & 7) == 0) {
            g_bits[(size_t)row * WORDS + warp * 32 + it * 4 + (lane >> 3)] = wbits;
            cnt += __popc(wbits);
        }
    }
    cnt += __shfl_xor_sync(0xFFFFFFFFu, cnt, 8);
    cnt += __shfl_xor_sync(0xFFFFFFFFu, cnt, 16);
    if (lane == 0) wcnt[warp] = cnt;
    __syncthreads();
    if (threadIdx.x == 0) {
        int deg = 1;
#pragma unroll
        for (int i = 0; i < 8; ++i) deg += wcnt[i];
        g_dinv[row] = rsqrtf((float)deg);
    }
}

// ---------------------------------------------------------------------------
// 2) small GEMM: ydraw = act @ [Wa|Wb] -> g_ydf0 (device-side ref!) + absmax
// ---------------------------------------------------------------------------
template <int KIN, int COUT>
__global__ void __launch_bounds__(256) small_gemm8(const float* __restrict__ act,
                                                   const float* __restrict__ Wa,
                                                   const float* __restrict__ Wb,
                                                   int slot) {
    __shared__ float sW[KIN * COUT];
    __shared__ float sact[16 * KIN];
    __shared__ unsigned int samax;

    int tid = threadIdx.x;
    if (tid == 0) samax = 0u;
    if (Wb == nullptr) {
        for (int i = tid; i < KIN * COUT; i += 256) sW[i] = Wa[i];
    } else {
        for (int i = tid; i < KIN * COUT; i += 256) {
            int k = i / COUT, c = i % COUT;
            sW[i] = (c < 64) ? Wa[k * 64 + c] : Wb[k * 64 + (c - 64)];
        }
    }

    int rbase = blockIdx.x * 16;
    for (int j = tid; j < 16 * KIN; j += 256)
        sact[j] = act[(size_t)rbase * KIN + j];
    __syncthreads();

    constexpr int TPR = COUT / 4;
    constexpr int RPI = 256 / TPR;
    int c4 = (tid % TPR) * 4;
    int ry0 = tid / TPR;
    float amax = 0.f;

#pragma unroll
    for (int it = 0; it < 16; it += RPI) {
        int ry = it + ry0;
        const float* sa = &sact[ry * KIN];
        float4 a0 = make_float4(0.f, 0.f, 0.f, 0.f);
        float4 a1 = make_float4(0.f, 0.f, 0.f, 0.f);
#pragma unroll
        for (int k = 0; k < KIN; k += 2) {
            float v0 = sa[k], v1 = sa[k + 1];
            float4 w0 = *(const float4*)&sW[k * COUT + c4];
            float4 w1 = *(const float4*)&sW[(k + 1) * COUT + c4];
            a0.x = fmaf(v0, w0.x, a0.x); a0.y = fmaf(v0, w0.y, a0.y);
            a0.z = fmaf(v0, w0.z, a0.z); a0.w = fmaf(v0, w0.w, a0.w);
            a1.x = fmaf(v1, w1.x, a1.x); a1.y = fmaf(v1, w1.y, a1.y);
            a1.z = fmaf(v1, w1.z, a1.z); a1.w = fmaf(v1, w1.w, a1.w);
        }
        int row = rbase + ry;
        float4 y;
        y.x = a0.x + a1.x; y.y = a0.y + a1.y;
        y.z = a0.z + a1.z; y.w = a0.w + a1.w;
        *(float4*)&g_ydf0[(size_t)row * COUT + c4] = y;   // device-side global ref
        amax = fmaxf(amax, fmaxf(fmaxf(fabsf(y.x), fabsf(y.y)),
                                 fmaxf(fabsf(y.z), fabsf(y.w))));
    }
    atomicMax(&samax, __float_as_uint(amax));
    __syncthreads();
    if (tid == 0) atomicMax(&g_absmax[slot], samax);
}

// ---------------------------------------------------------------------------
// 2b) convert: ydh = fp16(ydraw * dinv[row] * scale[slot])
// ---------------------------------------------------------------------------
__global__ void __launch_bounds__(256) convert_kernel(int slot, int C, int sel) {
    const float* ydf = sel ? g_ydf1 : g_ydf0;
    float s = layer_scale(slot);
    size_t i = ((size_t)blockIdx.x * 256 + threadIdx.x) * 4;
    int row = (int)(i / C);
    float ds = g_dinv[row] * s;
    float4 y = *(const float4*)&ydf[i];
    __half2 p01 = __floats2half2_rn(y.x * ds, y.y * ds);
    __half2 p23 = __floats2half2_rn(y.z * ds, y.w * ds);
    *(uint2*)&g_ydh[i] = make_uint2(*(uint32_t*)&p01, *(uint32_t*)&p23);
}

// ---------------------------------------------------------------------------
// 3) big adjacency GEMM (fp16 wmma): BM=128 x BN, split-K=4.
// ---------------------------------------------------------------------------
template <int BN, int MAXCTA>
__global__ void __launch_bounds__(256, MAXCTA) big_gcn9() {
    constexpr int BM    = 128;
    constexpr int KC    = 64;
    constexpr int NC    = (N / KSPLIT) / KC;
    constexpr int LDA   = 72;
    constexpr int LDB   = BN + 8;
    constexpr int ASZ   = BM * LDA;
    constexpr int BSZ   = KC * LDB;
    constexpr int WCOLS = (BN == 64) ? 2 : 4;
    constexpr int WROWS = 8 / WCOLS;
    constexpr int WM    = BM / WROWS;
    constexpr int WN    = BN / WCOLS;
    constexpr int FM    = WM / 16;
    constexpr int FN    = WN / 16;
    constexpr int SEG   = BN / 8;
    constexpr int CPB   = KC * SEG / 256;

    extern __shared__ __align__(16) __half smem[];
    __half* sA = smem;
    __half* sB = smem + 2 * ASZ;

    int tid  = threadIdx.x;
    int warp = tid >> 5;
    int wr   = warp / WCOLS;
    int wc   = warp % WCOLS;
    int r0   = blockIdx.x * BM;
    int ks0  = blockIdx.z * (N / KSPLIT);

    int arow = tid >> 1;
    const uint32_t* wptr = &g_bits[(size_t)(r0 + arow) * WORDS + (ks0 >> 5) + (tid & 1)];
    uint32_t abase = (uint32_t)__cvta_generic_to_shared(&sA[arow * LDA + (tid & 1) * 32]);

    wmma::fragment<wmma::accumulator, 16, 16, 16, float> acc[FM][FN];
#pragma unroll
    for (int fm = 0; fm < FM; ++fm)
#pragma unroll
        for (int fn = 0; fn < FN; ++fn) wmma::fill_fragment(acc[fm][fn], 0.f);

    auto fetchB = [&](int ch, int buf) {
        int k0 = ks0 + ch * KC;
#pragma unroll
        for (int i = 0; i < CPB; ++i) {
            int s = tid + i * 256;
            int row = s / SEG, seg = s % SEG;
            cp16(&sB[buf * BSZ + row * LDB + seg * 8],
                 &g_ydh[(size_t)(k0 + row) * BN + seg * 8]);
        }
        cp_commit();
    };
    auto storeA = [&](uint32_t w, int buf) {
        uint32_t base = abase + buf * (ASZ * 2);
#pragma unroll
        for (int j = 0; j < 4; ++j) {
            uint32_t bb = w >> (j * 8);
            uint4 u;
            u.x = ((bb & 1u)  ? 0x3C00u : 0u) | ((bb & 2u)   ? 0x3C000000u : 0u);
            u.y = ((bb & 4u)  ? 0x3C00u : 0u) | ((bb & 8u)   ? 0x3C000000u : 0u);
            u.z = ((bb & 16u) ? 0x3C00u : 0u) | ((bb & 32u)  ? 0x3C000000u : 0u);
            u.w = ((bb & 64u) ? 0x3C00u : 0u) | ((bb & 128u) ? 0x3C000000u : 0u);
            asm volatile("st.shared.v4.b32 [%0], {%1, %2, %3, %4};"
                         :: "r"(base + j * 16), "r"(u.x), "r"(u.y), "r"(u.z), "r"(u.w));
        }
    };

    fetchB(0, 0);
    storeA(wptr[0], 0);
    cp_wait0();
    __syncthreads();

    int buf = 0;
    for (int ch = 0; ch < NC; ++ch) {
        int nbuf = buf ^ 1;
        uint32_t wnext = 0;
        if (ch + 1 < NC) {
            fetchB(ch + 1, nbuf);
            wnext = wptr[(ch + 1) * 2];
        }
#pragma unroll
        for (int ks = 0; ks < 4; ++ks) {
            wmma::fragment<wmma::matrix_a, 16, 16, 16, __half, wmma::row_major> a[FM];
#pragma unroll
            for (int fm = 0; fm < FM; ++fm)
                wmma::load_matrix_sync(a[fm],
                    &sA[buf * ASZ + (wr * WM + fm * 16) * LDA + ks * 16], LDA);
#pragma unroll
            for (int fn = 0; fn < FN; ++fn) {
                wmma::fragment<wmma::matrix_b, 16, 16, 16, __half, wmma::row_major> b;
                int bcol = wc * WN + fn * 16;
                wmma::load_matrix_sync(b, &sB[buf * BSZ + (ks * 16) * LDB + bcol], LDB);
#pragma unroll
                for (int fm = 0; fm < FM; ++fm)
                    wmma::mma_sync(acc[fm][fn], a[fm], b, acc[fm][fn]);
            }
        }
        if (ch + 1 < NC) {
            storeA(wnext, nbuf);
            cp_wait0();
        }
        __syncthreads();
        buf = nbuf;
    }

    float* pout = &g_part[(size_t)blockIdx.z * N * BN];
#pragma unroll
    for (int fm = 0; fm < FM; ++fm)
#pragma unroll
        for (int fn = 0; fn < FN; ++fn)
            wmma::store_matrix_sync(
                &pout[(size_t)(r0 + wr * WM + fm * 16) * BN + wc * WN + fn * 16],
                acc[fm][fn], BN, wmma::mem_row_major);
}

constexpr int SMEM_BG9_128 = (2 * 128 * 72 + 2 * 64 * 136) * 2;  // 71680 B
constexpr int SMEM_BG9_64  = (2 * 128 * 72 + 2 * 64 * 72) * 2;   // 55296 B

// ---------------------------------------------------------------------------
// 3c) FUSED (KIN=64 variants only): combine(k) + GEMM(k+1), smem activation
// ---------------------------------------------------------------------------
template <int CIN, int KIN, int COUT>
__global__ void __launch_bounds__(256) fused_kernel(const float* __restrict__ bias_a,
                                                    const float* __restrict__ bias_b,
                                                    int bsplit, int slot_in, int slot_out,
                                                    const float* __restrict__ Wa,
                                                    int emit_reh, int in_sel, int act_c0) {
    __shared__ float sW[KIN * COUT];       // <= 32 KB
    __shared__ float sact[16 * CIN];
    __shared__ unsigned int samax;

    const float* ydin = in_sel ? g_ydf1 : g_ydf0;
    float* ydout = in_sel ? g_ydf0 : g_ydf1;

    int tid = threadIdx.x;
    if (tid == 0) samax = 0u;
    for (int i = tid; i < KIN * COUT; i += 256) sW[i] = Wa[i];

    float inv = layer_inv_scale(slot_in);
    int rbase = blockIdx.x * 16;
    constexpr int Q = 16 * CIN / 4;
    for (int idx = tid; idx < Q; idx += 256) {
        int r  = idx / (CIN / 4);
        int c4 = (idx % (CIN / 4)) * 4;
        int row = rbase + r;
        float di  = g_dinv[row];
        float dii = di * di;
        float dis = di * inv;
        size_t o = (size_t)row * CIN + c4;
        float4 p = make_float4(0.f, 0.f, 0.f, 0.f);
#pragma unroll
        for (int pz = 0; pz < KSPLIT; ++pz) {
            float4 pp = *(const float4*)&g_part[(size_t)pz * N * CIN + o];
            p.x += pp.x; p.y += pp.y; p.z += pp.z; p.w += pp.w;
        }
        float4 yd = *(const float4*)&ydin[o];
        const float* bias = (c4 < bsplit) ? bias_a : bias_b;
        int bo = (c4 < bsplit) ? c4 : c4 - bsplit;
        float4 v;
        v.x = p.x * dis + yd.x * dii + bias[bo + 0];
        v.y = p.y * dis + yd.y * dii + bias[bo + 1];
        v.z = p.z * dis + yd.z * dii + bias[bo + 2];
        v.w = p.w * dis + yd.w * dii + bias[bo + 3];
        v.x = (v.x > 0.f) ? v.x : 0.01f * v.x;
        v.y = (v.y > 0.f) ? v.y : 0.01f * v.y;
        v.z = (v.z > 0.f) ? v.z : 0.01f * v.z;
        v.w = (v.w > 0.f) ? v.w : 0.01f * v.w;
        *(float4*)&sact[r * CIN + c4] = v;
        if (emit_reh && c4 < 64) {
            __half2 h01 = __floats2half2_rn(v.x * 64.f, v.y * 64.f);
            __half2 h23 = __floats2half2_rn(v.z * 64.f, v.w * 64.f);
            *(uint2*)&g_reh[(size_t)row * 64 + c4] =
                make_uint2(*(uint32_t*)&h01, *(uint32_t*)&h23);
        }
    }
    __syncthreads();

    constexpr int TPR = COUT / 4;
    constexpr int RPI = 256 / TPR;
    int c4 = (tid % TPR) * 4;
    int ry0 = tid / TPR;
    float amax = 0.f;

#pragma unroll
    for (int it = 0; it < 16; it += RPI) {
        int ry = it + ry0;
        const float* sa = &sact[ry * CIN + act_c0];
        float4 a0 = make_float4(0.f, 0.f, 0.f, 0.f);
        float4 a1 = make_float4(0.f, 0.f, 0.f, 0.f);
#pragma unroll
        for (int k = 0; k < KIN; k += 2) {
            float v0 = sa[k], v1 = sa[k + 1];
            float4 w0 = *(const float4*)&sW[k * COUT + c4];
            float4 w1 = *(const float4*)&sW[(k + 1) * COUT + c4];
            a0.x = fmaf(v0, w0.x, a0.x); a0.y = fmaf(v0, w0.y, a0.y);
            a0.z = fmaf(v0, w0.z, a0.z); a0.w = fmaf(v0, w0.w, a0.w);
            a1.x = fmaf(v1, w1.x, a1.x); a1.y = fmaf(v1, w1.y, a1.y);
            a1.z = fmaf(v1, w1.z, a1.z); a1.w = fmaf(v1, w1.w, a1.w);
        }
        int row = rbase + ry;
        float4 y;
        y.x = a0.x + a1.x; y.y = a0.y + a1.y;
        y.z = a0.z + a1.z; y.w = a0.w + a1.w;
        *(float4*)&ydout[(size_t)row * COUT + c4] = y;
        amax = fmaxf(amax, fmaxf(fmaxf(fabsf(y.x), fabsf(y.y)),
                                 fmaxf(fabsf(y.z), fabsf(y.w))));
    }
    atomicMax(&samax, __float_as_uint(amax));
    __syncthreads();
    if (tid == 0) atomicMax(&g_absmax[slot_out], samax);
}

// ---------------------------------------------------------------------------
// 3b) standalone combine: out = lrelu(di*inv*Σpart + di²*ydraw + bias)
// ---------------------------------------------------------------------------
__global__ void __launch_bounds__(256) combine_kernel(const float* __restrict__ bias,
                                                      int C, int slot, int in_sel,
                                                      float* __restrict__ out) {
    const float* ydin = in_sel ? g_ydf1 : g_ydf0;
    float inv = layer_inv_scale(slot);
    int i = blockIdx.x * 256 + threadIdx.x;
    int cq = C >> 2;
    int row = i / cq;
    int c4  = (i - row * cq) * 4;
    float di  = g_dinv[row];
    float dii = di * di;
    float dis = di * inv;
    size_t o = (size_t)row * C + c4;
    float4 p = make_float4(0.f, 0.f, 0.f, 0.f);
#pragma unroll
    for (int pz = 0; pz < KSPLIT; ++pz) {
        float4 pp = *(const float4*)&g_part[(size_t)pz * N * C + o];
        p.x += pp.x; p.y += pp.y; p.z += pp.z; p.w += pp.w;
    }
    float4 yd = *(const float4*)&ydin[o];
    float4 v;
    v.x = p.x * dis + yd.x * dii + bias[c4 + 0];
    v.y = p.y * dis + yd.y * dii + bias[c4 + 1];
    v.z = p.z * dis + yd.z * dii + bias[c4 + 2];
    v.w = p.w * dis + yd.w * dii + bias[c4 + 3];
    v.x = (v.x > 0.f) ? v.x : 0.01f * v.x;
    v.y = (v.y > 0.f) ? v.y : 0.01f * v.y;
    v.z = (v.z > 0.f) ? v.z : 0.01f * v.z;
    v.w = (v.w > 0.f) ? v.w : 0.01f * v.w;
    *(float4*)&out[o] = v;
}

// ---------------------------------------------------------------------------
// 5) recon = sigmoid((reh @ reh^T) / 4096), triangular 1-D grid, fp16
// ---------------------------------------------------------------------------
__device__ __forceinline__ float fsig(float x) {
    return __fdividef(1.f, 1.f + __expf(-x));
}

constexpr int RLD  = 72;
constexpr int RLDC = 132;
constexpr int SMEM_RECON = 128 * RLDC * 4;  // 67584 B

__global__ void __launch_bounds__(256, 2) recon_kernel(float* __restrict__ out) {
    int bid = blockIdx.x;
    int by = (int)((sqrtf(8.f * (float)bid + 1.f) - 1.f) * 0.5f);
    while ((by + 1) * (by + 2) / 2 <= bid) ++by;
    while (by * (by + 1) / 2 > bid) --by;
    int bx = bid - by * (by + 1) / 2;

    extern __shared__ __align__(16) __half smem2[];
    __half* sA = smem2;
    __half* sB = smem2 + 128 * RLD;

    int tid = threadIdx.x;
    int r0 = by * 128, c0 = bx * 128;

    int srow = tid >> 1;
    int soff = (tid & 1) * 32;
    {
        const uint4* s;
        uint4* d;
        s = (const uint4*)&g_reh[(size_t)(r0 + srow) * 64 + soff];
        d = (uint4*)&sA[srow * RLD + soff];
        d[0] = s[0]; d[1] = s[1]; d[2] = s[2]; d[3] = s[3];
        s = (const uint4*)&g_reh[(size_t)(c0 + srow) * 64 + soff];
        d = (uint4*)&sB[srow * RLD + soff];
        d[0] = s[0]; d[1] = s[1]; d[2] = s[2]; d[3] = s[3];
    }
    __syncthreads();

    int warp = tid >> 5;
    int lane = tid & 31;
    int wr = warp >> 2;
    int wc = warp & 3;

    wmma::fragment<wmma::accumulator, 16, 16, 16, float> acc[4][2];
#pragma unroll
    for (int fm = 0; fm < 4; ++fm)
#pragma unroll
        for (int fn = 0; fn < 2; ++fn) wmma::fill_fragment(acc[fm][fn], 0.f);

#pragma unroll
    for (int ks = 0; ks < 4; ++ks) {
        int k = ks * 16;
        wmma::fragment<wmma::matrix_a, 16, 16, 16, __half, wmma::row_major> a[4];
#pragma unroll
        for (int fm = 0; fm < 4; ++fm)
            wmma::load_matrix_sync(a[fm], &sA[(wr * 64 + fm * 16) * RLD + k], RLD);
#pragma unroll
        for (int fn = 0; fn < 2; ++fn) {
            int col = wc * 32 + fn * 16;
            wmma::fragment<wmma::matrix_b, 16, 16, 16, __half, wmma::col_major> b;
            wmma::load_matrix_sync(b, &sB[col * RLD + k], RLD);
#pragma unroll
            for (int fm = 0; fm < 4; ++fm)
                wmma::mma_sync(acc[fm][fn], a[fm], b, acc[fm][fn]);
        }
    }
    __syncthreads();

    float* sC = reinterpret_cast<float*>(smem2);
#pragma unroll
    for (int fm = 0; fm < 4; ++fm)
#pragma unroll
        for (int fn = 0; fn < 2; ++fn)
            wmma::store_matrix_sync(&sC[(wr * 64 + fm * 16) * RLDC + wc * 32 + fn * 16],
                                    acc[fm][fn], RLDC, wmma::mem_row_major);
    __syncthreads();

    constexpr float INVS = 1.f / 4096.f;
#pragma unroll
    for (int it = 0; it < 16; ++it) {
        int f4 = tid + it * 256;
        int r  = f4 >> 5;
        int c4 = (f4 & 31) << 2;
        float4 o;
        o.x = fsig(sC[r * RLDC + c4 + 0] * INVS);
        o.y = fsig(sC[r * RLDC + c4 + 1] * INVS);
        o.z = fsig(sC[r * RLDC + c4 + 2] * INVS);
        o.w = fsig(sC[r * RLDC + c4 + 3] * INVS);
        *(float4*)&out[(size_t)(r0 + r) * N + c0 + c4] = o;
    }
    if (bx != by) {
#pragma unroll
        for (int i = 0; i < 16; ++i) {
            int c = warp * 16 + i;
#pragma unroll
            for (int q = 0; q < 4; ++q) {
                float v = sC[c * RLDC + q * 32 + lane] * INVS;
                out[(size_t)(c0 + c) * N + r0 + q * 32 + lane] = fsig(v);
            }
        }
    }
}

// ---------------------------------------------------------------------------
// Launch chain.  Fork 1: small_gemm (s2) ∥ prep (main).
// Fork 2: recon (s2) ∥ layer-5 chain (main).  #4 = big_gcn9<64,3> (profiled)
// ---------------------------------------------------------------------------
extern "C" void kernel_launch(void* const* d_in, const int* in_sizes, int n_in,
                              void* d_out, int out_size) {
    (void)in_sizes; (void)n_in; (void)out_size;
    const float* x    = (const float*)d_in[0];
    const int*   edge = (const int*)  d_in[1];
    const float* W1   = (const float*)d_in[2];
    const float* b1   = (const float*)d_in[3];
    const float* W2   = (const float*)d_in[4];
    const float* b2   = (const float*)d_in[5];
    const float* We   = (const float*)d_in[6];
    const float* be   = (const float*)d_in[7];
    const float* Wd1  = (const float*)d_in[8];
    const float* bd1  = (const float*)d_in[9];
    const float* Wd2  = (const float*)d_in[10];
    const float* bd2  = (const float*)d_in[11];

    float* out   = (float*)d_out;
    float* recon = out;
    float* xout  = out + (size_t)N * N;
    float* zout  = xout + (size_t)N * 128;

    cudaFuncSetAttribute(big_gcn9<128, 2>, cudaFuncAttributeMaxDynamicSharedMemorySize, SMEM_BG9_128);
    cudaFuncSetAttribute(big_gcn9<64, 3>,  cudaFuncAttributeMaxDynamicSharedMemorySize, SMEM_BG9_64);
    cudaFuncSetAttribute(recon_kernel,     cudaFuncAttributeMaxDynamicSharedMemorySize, SMEM_RECON);

    // ---- fork 1: layer-1 small_gemm (s2) ∥ prep (main) ----
    if (g_ov.ok) {
        cudaEventRecord(g_ov.evFork1, 0);
        cudaStreamWaitEvent(g_ov.s2, g_ov.evFork1, 0);
        small_gemm8<128, 64><<<512, 256, 0, g_ov.s2>>>(x, W1, nullptr, 0);          // #1
        cudaEventRecord(g_ov.evJoin1, g_ov.s2);
        prep_kernel<<<N, 256>>>(edge);                                              // #2
        cudaStreamWaitEvent(0, g_ov.evJoin1, 0);
    } else {
        small_gemm8<128, 64><<<512, 256>>>(x, W1, nullptr, 0);
        prep_kernel<<<N, 256>>>(edge);
    }
    convert_kernel<<<N * 64 / 1024, 256>>>(0, 64, 0);                               // #3
    big_gcn9<64, 3><<<dim3(64, 1, KSPLIT), 256, SMEM_BG9_64>>>();                   // #4 <- profiled

    // fusedA: combine1 (h, smem-only) + h@W2 -> ydf1, slot1
    fused_kernel<64, 64, 128><<<512, 256>>>(b1, b1, 64, 0, 1, W2, 0, 0, 0);         // #5
    convert_kernel<<<N * 128 / 1024, 256>>>(1, 128, 1);                             // #6
    big_gcn9<128, 2><<<dim3(64, 1, KSPLIT), 256, SMEM_BG9_128>>>();                 // #7

    // layer 3/4 front: combine2 -> zout (model output), then z@[We|Wd1] -> ydf0
    combine_kernel<<<N * 128 / 1024, 256>>>(b2, 128, 1, 1, zout);                   // #8
    small_gemm8<128, 128><<<512, 256>>>(zout, We, Wd1, 2);                          // #9
    convert_kernel<<<N * 128 / 1024, 256>>>(2, 128, 0);                             // #10
    big_gcn9<128, 2><<<dim3(64, 1, KSPLIT), 256, SMEM_BG9_128>>>();                 // #11

    // fusedC: combine3 ([re|xd], smem-only) + xd@Wd2 -> ydf1, slot3; emits g_reh
    fused_kernel<128, 64, 128><<<512, 256>>>(be, bd1, 64, 2, 3, Wd2, 1, 0, 64);     // #12

    constexpr int TRI = 64 * 65 / 2;   // 2080 tiles

    if (g_ov.ok) {
        // fork 2: recon (s2) ∥ layer-5 chain (main)
        cudaEventRecord(g_ov.evFork2, 0);
        cudaStreamWaitEvent(g_ov.s2, g_ov.evFork2, 0);
        recon_kernel<<<TRI, 256, SMEM_RECON, g_ov.s2>>>(recon);

        convert_kernel<<<N * 128 / 1024, 256>>>(3, 128, 1);
        big_gcn9<128, 2><<<dim3(64, 1, KSPLIT), 256, SMEM_BG9_128>>>();
        combine_kernel<<<N * 128 / 1024, 256>>>(bd2, 128, 3, 1, xout);

        cudaEventRecord(g_ov.evJoin2, g_ov.s2);
        cudaStreamWaitEvent(0, g_ov.evJoin2, 0);
    } else {
        convert_kernel<<<N * 128 / 1024, 256>>>(3, 128, 1);
        big_gcn9<128, 2><<<dim3(64, 1, KSPLIT), 256, SMEM_BG9_128>>>();
        combine_kernel<<<N * 128 / 1024, 256>>>(bd2, 128, 3, 1, xout);
        recon_kernel<<<TRI, 256, SMEM_RECON>>>(recon);
    }
}